// round 16
// baseline (speedup 1.0000x reference)
#include <cuda_runtime.h>
#include <math.h>
#include <stdint.h>

// EncoderSRNN GB300 R15: R14 base + stack rows 1-63 update moved into the
// cluster-wait latency window (only row 0 + tops remain post-wait).
// 32 clusters x 4 CTAs, 4 batch lanes per cluster.

#define T_STEPS 256
#define BATCH   128
#define HDIM    256
#define SDIM    64
#define SSZ     64
#define NT      512
#define NKW     40     // k per mhid warp; k = warp + 16*i (strided)

typedef unsigned long long ull;

struct __align__(16) SM {
    float4 x4[2][640];          // [parity][k] = {b0,b1,b2,b3}
    float4 partm[16][65];       // mhid partials (padded)
    float4 parts[40][33];       // 0-15 pv, 16-31 uv, 32-39 head halves
    float  stck[2][SSZ][SDIM];  // own-lane stack dbl-buf
    float  pvb[2][SDIM][4];     // push_val [p][d][b]
    float  uvb[2][SDIM][4];     // u_val
    float  s2b[2][4][SDIM];     // old stack row2 [p][b][d]
    float  Whs[16][256];        // own 16 pv rows
    float  Wsu[16][128];
    float  Whd[4][256];         // head rows (W_ha 0-2, W_hg 3)
    float  outst[4][64];        // staged outputs [b][r]
    int    toks[T_STEPS][4];    // token ids for this cluster's 4 lanes
    float  biasm[64];
    float  bhs[16], bsu[16], bhd[4];
    float  lg[4][4];            // [b][head]
    float  pr[4][4];            // [b][push,pop,noop]
    ull    mbar;
};

__device__ __forceinline__ uint32_t s32(const void* p) {
    return (uint32_t)__cvta_generic_to_shared(p);
}
__device__ __forceinline__ uint32_t mapa_r(uint32_t a, uint32_t r) {
    uint32_t ra;
    asm("mapa.shared::cluster.u32 %0, %1, %2;" : "=r"(ra) : "r"(a), "r"(r));
    return ra;
}
__device__ __forceinline__ void stcv4(uint32_t addr, float a, float b, float c, float d) {
    asm volatile("st.shared::cluster.v4.f32 [%0], {%1,%2,%3,%4};"
                 :: "r"(addr), "f"(a), "f"(b), "f"(c), "f"(d) : "memory");
}
__device__ __forceinline__ uint32_t ctarank() {
    uint32_t r; asm("mov.u32 %0, %%cluster_ctarank;" : "=r"(r)); return r;
}
__device__ __forceinline__ ull ffma2(ull a, ull b, ull c) {
    ull d; asm("fma.rn.f32x2 %0, %1, %2, %3;" : "=l"(d) : "l"(a), "l"(b), "l"(c)); return d;
}
__device__ __forceinline__ ull bcast2(float f) {
    ull d; asm("mov.b64 %0, {%1, %1};" : "=l"(d) : "f"(f)); return d;
}
__device__ __forceinline__ float2 unpk(ull v) {
    float2 u; asm("mov.b64 {%0, %1}, %2;" : "=f"(u.x), "=f"(u.y) : "l"(v)); return u;
}
__device__ __forceinline__ float loadW(const float* We, const float* Wh,
                                       const float* Ws, int R, int k) {
    if (k < 256) return We[R * 256 + k];
    if (k < 512) return Wh[R * 256 + (k - 256)];
    return Ws[R * 128 + (k - 512)];
}

template<int NM>
__device__ __forceinline__ void small1(const float* W0, const ulonglong2* xb,
                                       int koff, int lane, float4* d0) {
    ull a0 = 0, a1 = 0;
    #pragma unroll
    for (int m = 0; m < NM; ++m) {
        int kk = lane + 32 * m;
        ulonglong2 xx = xb[koff + kk];
        ull w = bcast2(W0[kk]);
        a0 = ffma2(w, xx.x, a0);
        a1 = ffma2(w, xx.y, a1);
    }
    float2 u0 = unpk(a0), u1 = unpk(a1);
    *d0 = make_float4(u0.x, u0.y, u1.x, u1.y);
}

template<int NM>
__device__ __forceinline__ void small2(const float* W0, const float* W1,
                                       const ulonglong2* xb, int koff, int lane,
                                       float4* d0, float4* d1) {
    ull a00 = 0, a01 = 0, a10 = 0, a11 = 0;
    #pragma unroll
    for (int m = 0; m < NM; ++m) {
        int kk = lane + 32 * m;
        ulonglong2 xx = xb[koff + kk];
        ull w0 = bcast2(W0[kk]);
        a00 = ffma2(w0, xx.x, a00);
        a01 = ffma2(w0, xx.y, a01);
        ull w1 = bcast2(W1[kk]);
        a10 = ffma2(w1, xx.x, a10);
        a11 = ffma2(w1, xx.y, a11);
    }
    float2 u0 = unpk(a00), u1 = unpk(a01);
    *d0 = make_float4(u0.x, u0.y, u1.x, u1.y);
    float2 v0 = unpk(a10), v1 = unpk(a11);
    *d1 = make_float4(v0.x, v0.y, v1.x, v1.y);
}

__global__ void __launch_bounds__(NT, 1) __cluster_dims__(4, 1, 1)
srnn_kernel(const int*   __restrict__ inputs,
            const float* __restrict__ emb_W,
            const float* __restrict__ W_hh, const float* __restrict__ b_hh,
            const float* __restrict__ W_eh, const float* __restrict__ b_eh,
            const float* __restrict__ W_ha, const float* __restrict__ b_ha,
            const float* __restrict__ W_hg, const float* __restrict__ b_hg,
            const float* __restrict__ W_hs, const float* __restrict__ b_hs,
            const float* __restrict__ W_sh, const float* __restrict__ b_sh,
            const float* __restrict__ W_su, const float* __restrict__ b_su,
            const float* __restrict__ empty_elem,
            float* __restrict__ out)
{
    extern __shared__ char raw[];
    SM* sm = reinterpret_cast<SM*>(raw);

    const int tid  = threadIdx.x;
    const int warp = tid >> 5;
    const int lane = tid & 31;
    const uint32_t rank = ctarank();
    const int clus = blockIdx.x >> 2;

    float* out_outputs = out;
    float* out_hid     = out + (size_t)T_STEPS * BATCH * HDIM;
    float* out_stack   = out_hid + BATCH * HDIM;
    float* out_acts    = out_stack + (size_t)BATCH * SSZ * SDIM;

    const uint32_t x4_l  = s32(&sm->x4[0][0]);
    const uint32_t pv_l  = s32(&sm->pvb[0][0][0]);
    const uint32_t uv_l  = s32(&sm->uvb[0][0][0]);
    const uint32_t s2_l  = s32(&sm->s2b[0][0][0]);
    const uint32_t mbar_l = s32(&sm->mbar);

    // ===================== init =====================
    float wr0[NKW], wr1[NKW];
    {
        int R0 = 64 * (int)rank + lane, R1 = R0 + 32;
        #pragma unroll
        for (int i = 0; i < NKW; ++i) {
            int k = warp + 16 * i;
            wr0[i] = loadW(W_eh, W_hh, W_sh, R0, k);
            wr1[i] = loadW(W_eh, W_hh, W_sh, R1, k);
        }
    }
    for (int idx = tid; idx < 16 * 256; idx += NT) {
        int r = idx >> 8, k = idx & 255;
        sm->Whs[r][k] = W_hs[(16 * rank + r) * 256 + k];
    }
    for (int idx = tid; idx < 16 * 128; idx += NT) {
        int r = idx >> 7, k = idx & 127;
        sm->Wsu[r][k] = W_su[(16 * rank + r) * 128 + k];
    }
    for (int idx = tid; idx < 4 * 256; idx += NT) {
        int r = idx >> 8, k = idx & 255;
        sm->Whd[r][k] = (r < 3) ? W_ha[r * 256 + k] : W_hg[k];
    }
    for (int e = tid; e < T_STEPS * 4; e += NT) {
        sm->toks[e >> 2][e & 3] = inputs[(e >> 2) * BATCH + clus * 4 + (e & 3)];
    }
    if (tid < 64) {
        int R = 64 * rank + tid;
        sm->biasm[tid] = b_eh[R] + b_hh[R] + b_sh[R];
        if (tid < 16) {
            sm->bhs[tid] = b_hs[16 * rank + tid];
            sm->bsu[tid] = b_su[16 * rank + tid];
        }
        if (tid < 4) sm->bhd[tid] = (tid < 3) ? b_ha[tid] : b_hg[0];
    }
    if (tid == 0) {
        asm volatile("mbarrier.init.shared.b64 [%0], %1;"
                     :: "r"(mbar_l), "r"(4) : "memory");
    }
    for (int e = tid; e < 640 * 4; e += NT) {
        int k = e >> 2, b = e & 3;
        float v;
        if (k < 256) {
            int row = inputs[clus * 4 + b];
            v = emb_W[(size_t)row * 256 + k];
        } else if (k < 512) v = 0.f;
        else                v = empty_elem[(k - 512) & 63];
        ((float*)&sm->x4[0][k])[b] = v;
    }
    for (int e = tid; e < SSZ * SDIM; e += NT)
        sm->stck[0][e >> 6][e & 63] = empty_elem[e & 63];
    __syncthreads();
    asm volatile("barrier.cluster.arrive.aligned;" ::: "memory");
    asm volatile("barrier.cluster.wait.aligned;" ::: "memory");

    // mhid accumulators persist across barriers (emb segment pipelined)
    ull a00, a01, a10, a11;
    {
        a00 = a01 = a10 = a11 = 0;
        const ulonglong2* xv = reinterpret_cast<const ulonglong2*>(&sm->x4[0][0]);
        #pragma unroll
        for (int i = 0; i < 16; ++i) {
            ulonglong2 xx = xv[warp + 16 * i];
            ull w0 = bcast2(wr0[i]);
            a00 = ffma2(w0, xx.x, a00);
            a01 = ffma2(w0, xx.y, a01);
            ull w1 = bcast2(wr1[i]);
            a10 = ffma2(w1, xx.x, a10);
            a11 = ffma2(w1, xx.y, a11);
        }
    }

    // ===================== time loop =====================
    for (int t = 0; t < T_STEPS; ++t) {
        const int p = t & 1;

        // ---------- A1 ----------
        float pe0, pe1;
        {
            int tn = (t + 1 < T_STEPS) ? t + 1 : T_STEPS - 1;
            int b = tid >> 7, k = tid & 127;
            int row = sm->toks[tn][b];
            pe0 = emb_W[(size_t)row * 256 + k];
            pe1 = emb_W[(size_t)row * 256 + k + 128];
        }
        {
            const ulonglong2* xv = reinterpret_cast<const ulonglong2*>(&sm->x4[p][0]);
            #pragma unroll
            for (int i = 16; i < NKW; ++i) {
                ulonglong2 xx = xv[warp + 16 * i];
                ull w0 = bcast2(wr0[i]);
                a00 = ffma2(w0, xx.x, a00);
                a01 = ffma2(w0, xx.y, a01);
                ull w1 = bcast2(wr1[i]);
                a10 = ffma2(w1, xx.x, a10);
                a11 = ffma2(w1, xx.y, a11);
            }
            float2 u0 = unpk(a00), u1 = unpk(a01);
            sm->partm[warp][lane]      = make_float4(u0.x, u0.y, u1.x, u1.y);
            float2 v0 = unpk(a10), v1 = unpk(a11);
            sm->partm[warp][lane + 32] = make_float4(v0.x, v0.y, v1.x, v1.y);
        }
        const ulonglong2* xb = reinterpret_cast<const ulonglong2*>(&sm->x4[p][0]);
        if (warp < 8) {                 // pv rows {2w, 2w+1}
            int r0 = 2 * warp;
            small2<8>(sm->Whs[r0], sm->Whs[r0 + 1], xb, 256, lane,
                      &sm->parts[r0][lane], &sm->parts[r0 + 1][lane]);
        } else {                        // uv rows {2(w-8), 2(w-8)+1} + head half
            int r0 = 2 * (warp - 8);
            small2<4>(sm->Wsu[r0], sm->Wsu[r0 + 1], xb, 512, lane,
                      &sm->parts[16 + r0][lane], &sm->parts[16 + r0 + 1][lane]);
            int h = (warp - 8) & 3;
            const float* Wr = sm->Whd[h] + ((warp < 12) ? 0 : 128);
            small1<4>(Wr, xb, (warp < 12) ? 256 : 384, lane,
                      &sm->parts[32 + (warp - 8)][lane]);
        }
        {   // emb(t+1) into x4[p^1]
            int b = tid >> 7, k = tid & 127;
            float* dst = (float*)&sm->x4[p ^ 1][0];
            dst[k * 4 + b]         = pe0;
            dst[(k + 128) * 4 + b] = pe1;
        }
        __syncthreads();   // bar 1

        // ---------- A2: reduce + lane-spread DSMEM broadcast + probs ----------
        if (tid < 256) {                // mhid: 4 threads per row
            int r = tid >> 2, q = tid & 3;
            float4 s4 = sm->partm[q * 4][r];
            #pragma unroll
            for (int j = 1; j < 4; ++j) {
                float4 v = sm->partm[q * 4 + j][r];
                s4.x += v.x; s4.y += v.y; s4.z += v.z; s4.w += v.w;
            }
            #pragma unroll
            for (int o = 1; o <= 2; o <<= 1) {
                s4.x += __shfl_xor_sync(0xffffffffu, s4.x, o);
                s4.y += __shfl_xor_sync(0xffffffffu, s4.y, o);
                s4.z += __shfl_xor_sync(0xffffffffu, s4.z, o);
                s4.w += __shfl_xor_sync(0xffffffffu, s4.w, o);
            }
            float bb = sm->biasm[r];
            float h0 = fmaxf(s4.x + bb, 0.f), h1 = fmaxf(s4.y + bb, 0.f);
            float h2 = fmaxf(s4.z + bb, 0.f), h3 = fmaxf(s4.w + bb, 0.f);
            int R = 64 * rank + r;
            uint32_t off = x4_l + (uint32_t)((p ^ 1) * 640 + 256 + R) * 16u;
            stcv4(mapa_r(off, (uint32_t)q), h0, h1, h2, h3);
            if (q == 1) {               // outputs staging
                sm->outst[0][r] = h0;
                sm->outst[1][r] = h1;
                sm->outst[2][r] = h2;
                sm->outst[3][r] = h3;
            }
        } else if (tid < 416) {         // small rows reduce (warps 8-12)
            int e = tid - 256;
            int vr = e >> 2, s = e & 3;
            float4 acc = make_float4(0.f, 0.f, 0.f, 0.f);
            #pragma unroll
            for (int u = 0; u < 8; ++u) {
                float4 v = sm->parts[vr][s + 4 * u];
                acc.x += v.x; acc.y += v.y; acc.z += v.z; acc.w += v.w;
            }
            #pragma unroll
            for (int o = 1; o <= 2; o <<= 1) {
                acc.x += __shfl_xor_sync(0xffffffffu, acc.x, o);
                acc.y += __shfl_xor_sync(0xffffffffu, acc.y, o);
                acc.z += __shfl_xor_sync(0xffffffffu, acc.z, o);
                acc.w += __shfl_xor_sync(0xffffffffu, acc.w, o);
            }
            if (vr >= 32) {             // heads: combine two k-halves (warp 12)
                acc.x += __shfl_xor_sync(0xffffffffu, acc.x, 16);
                acc.y += __shfl_xor_sync(0xffffffffu, acc.y, 16);
                acc.z += __shfl_xor_sync(0xffffffffu, acc.z, 16);
                acc.w += __shfl_xor_sync(0xffffffffu, acc.w, 16);
            }
            if (vr < 16) {              // pv -> CTA s (each lane one dest)
                float bb = sm->bhs[vr];
                int dd = 16 * (int)rank + vr;
                uint32_t off = pv_l + (uint32_t)(p * 64 + dd) * 16u;
                stcv4(mapa_r(off, (uint32_t)s),
                      fmaxf(acc.x + bb, 0.f), fmaxf(acc.y + bb, 0.f),
                      fmaxf(acc.z + bb, 0.f), fmaxf(acc.w + bb, 0.f));
            } else if (vr < 32) {       // uv -> CTA s
                float bb = sm->bsu[vr - 16];
                int dd = 16 * (int)rank + (vr - 16);
                uint32_t off = uv_l + (uint32_t)(p * 64 + dd) * 16u;
                stcv4(mapa_r(off, (uint32_t)s),
                      fmaxf(acc.x + bb, 0.f), fmaxf(acc.y + bb, 0.f),
                      fmaxf(acc.z + bb, 0.f), fmaxf(acc.w + bb, 0.f));
            } else if (s == 0 && vr < 36) {
                int h = vr - 32;
                float bb = sm->bhd[h];
                sm->lg[0][h] = acc.x + bb;
                sm->lg[1][h] = acc.y + bb;
                sm->lg[2][h] = acc.z + bb;
                sm->lg[3][h] = acc.w + bb;
            }
            if (warp == 12) {           // probs inline
                __syncwarp();
                if (lane < 4) {
                    int b = lane;
                    float l0 = sm->lg[b][0], l1 = sm->lg[b][1], l2 = sm->lg[b][2];
                    float g  = sm->lg[b][3];
                    float ssp = (g > 20.f) ? g : log1pf(expf(g));
                    float gamma = 1.f + ssp;
                    float mx = fmaxf(l0, fmaxf(l1, l2));
                    float e0 = expf(l0 - mx), e1 = expf(l1 - mx), e2 = expf(l2 - mx);
                    float ls = logf(e0 + e1 + e2);
                    float s0 = expf(gamma * ((l0 - mx) - ls));
                    float s1 = expf(gamma * ((l1 - mx) - ls));
                    float s2 = expf(gamma * ((l2 - mx) - ls));
                    float inv = 1.f / (s0 + s1 + s2 + 1e-16f);
                    sm->pr[b][0] = s0 * inv;
                    sm->pr[b][1] = s1 * inv;
                    sm->pr[b][2] = s2 * inv;
                    if ((uint32_t)b == rank) {
                        int idx = 0; float best = s0;
                        if (s1 > best) { best = s1; idx = 1; }
                        if (s2 > best) idx = 2;
                        out_acts[t * BATCH + clus * 4 + rank] = (float)idx;
                    }
                }
            }
        } else if (tid < 480) {         // s2 broadcast: 64 threads, 1 store each
            int t2 = tid - 416;         // 0..63
            int d = t2 >> 4, i16 = t2 & 15;
            const float4* s2src = reinterpret_cast<const float4*>(&sm->stck[p][2][0]);
            float4 v = s2src[i16];
            uint32_t off = s2_l + (uint32_t)((p * 4 + rank) * 64 + 4 * i16) * 4u;
            stcv4(mapa_r(off, (uint32_t)d), v.x, v.y, v.z, v.w);
        }
        __syncthreads();   // bar 2

        // ---------- signal peers (release; bar2 gives cumulativity) ----------
        if (tid < 4) {
            asm volatile("mbarrier.arrive.release.cluster.shared::cluster.b64 _, [%0];"
                         :: "r"(mapa_r(mbar_l, (uint32_t)tid)) : "memory");
        }

        // ---------- window: stack rows 1-63 + outputs STG + next emb segment ----------
        if (tid < 256) {   // stack rows 1..63 need only pr (local) + own stack
            int d4 = tid & 15, ic = tid >> 4;
            const float4* Ssrc = (const float4*)sm->stck[p];
            float4*       Sdst = (float4*)sm->stck[p ^ 1];
            float pp = sm->pr[rank][0], pq = sm->pr[rank][1], pn = sm->pr[rank][2];
            float4 prev = Ssrc[((ic == 0) ? 0 : (4 * ic - 1)) * 16 + d4];
            float4 curv = Ssrc[(4 * ic) * 16 + d4];
            #pragma unroll
            for (int ii = 0; ii < 4; ++ii) {
                int i = 4 * ic + ii;
                float4 nxt = (i < 63) ? Ssrc[(i + 1) * 16 + d4]
                                      : make_float4(0.f, 0.f, 0.f, 0.f);
                float4 nv;
                nv.x = pp * prev.x + pq * nxt.x + pn * curv.x;
                nv.y = pp * prev.y + pq * nxt.y + pn * curv.y;
                nv.z = pp * prev.z + pq * nxt.z + pn * curv.z;
                nv.w = pp * prev.w + pq * nxt.w + pn * curv.w;
                if (i >= 1) Sdst[i * 16 + d4] = nv;
                prev = curv; curv = nxt;
            }
        } else if (tid >= 480) {        // outputs STG from stage
            int j = tid - 480;            // 0..31
            #pragma unroll
            for (int jj = 0; jj < 2; ++jj) {
                int e = j + 32 * jj;      // 0..63
                int b = e >> 4, rr = e & 15;
                const float4* src = reinterpret_cast<const float4*>(&sm->outst[b][0]);
                float4 v = src[rr];
                size_t ob = ((size_t)t * BATCH + clus * 4 + b) * HDIM + 64 * rank + 4 * rr;
                *reinterpret_cast<float4*>(&out_outputs[ob]) = v;
            }
        }
        {   // emb segment for t+1 over x4[p^1].emb
            a00 = a01 = a10 = a11 = 0;
            const ulonglong2* xv = reinterpret_cast<const ulonglong2*>(&sm->x4[p ^ 1][0]);
            #pragma unroll
            for (int i = 0; i < 16; ++i) {
                ulonglong2 xx = xv[warp + 16 * i];
                ull w0 = bcast2(wr0[i]);
                a00 = ffma2(w0, xx.x, a00);
                a01 = ffma2(w0, xx.y, a01);
                ull w1 = bcast2(wr1[i]);
                a10 = ffma2(w1, xx.x, a10);
                a11 = ffma2(w1, xx.y, a11);
            }
        }

        // ---------- wait for all 4 CTAs' exchanges (acquire) ----------
        {
            uint32_t parity = (uint32_t)(t & 1);
            asm volatile(
                "{\n\t"
                ".reg .pred P;\n"
                "W%=:\n\t"
                "mbarrier.try_wait.parity.acquire.cluster.shared::cta.b64 P, [%0], %1, 0x989680;\n\t"
                "@!P bra W%=;\n\t"
                "}"
                :: "r"(mbar_l), "r"(parity) : "memory");
        }

        // ---------- B (post-wait, tiny): stack row 0 + new tops ----------
        if (tid < 16) {
            int d4 = tid;
            const float4* Ssrc = (const float4*)sm->stck[p];
            float4*       Sdst = (float4*)sm->stck[p ^ 1];
            float pp = sm->pr[rank][0], pq = sm->pr[rank][1], pn = sm->pr[rank][2];
            float4 old0 = Ssrc[d4];
            float4 pv4 = make_float4(sm->pvb[p][d4 * 4 + 0][rank],
                                     sm->pvb[p][d4 * 4 + 1][rank],
                                     sm->pvb[p][d4 * 4 + 2][rank],
                                     sm->pvb[p][d4 * 4 + 3][rank]);
            float4 uv4 = make_float4(sm->uvb[p][d4 * 4 + 0][rank],
                                     sm->uvb[p][d4 * 4 + 1][rank],
                                     sm->uvb[p][d4 * 4 + 2][rank],
                                     sm->uvb[p][d4 * 4 + 3][rank]);
            float4 nv;
            nv.x = pp * pv4.x + pq * uv4.x + pn * old0.x;
            nv.y = pp * pv4.y + pq * uv4.y + pn * old0.y;
            nv.z = pp * pv4.z + pq * uv4.z + pn * old0.z;
            nv.w = pp * pv4.w + pq * uv4.w + pn * old0.w;
            Sdst[d4] = nv;
        } else if (tid >= 256) {
            int e0 = tid - 256;
            #pragma unroll
            for (int j = 0; j < 2; ++j) {
                int e = e0 + j * 256;              // 0..511
                int b = e >> 7, row = (e >> 6) & 1, d = e & 63;
                float pp = sm->pr[b][0], pq = sm->pr[b][1], pn = sm->pr[b][2];
                float old0 = ((float*)&sm->x4[p][512 + d])[b];
                float nv;
                if (row == 0) {
                    nv = pp * sm->pvb[p][d][b] + pq * sm->uvb[p][d][b] + pn * old0;
                } else {
                    float old1 = ((float*)&sm->x4[p][576 + d])[b];
                    nv = pp * old0 + pq * sm->s2b[p][b][d] + pn * old1;
                }
                ((float*)&sm->x4[p ^ 1][512 + row * 64 + d])[b] = nv;
            }
        }
        __syncthreads();   // bar 3
    }

    // ===================== final outputs =====================
    {
        int bg = clus * 4 + rank;
        if (tid < 256)
            out_hid[bg * HDIM + tid] = ((float*)&sm->x4[0][256 + tid])[rank];
        for (int e = tid; e < SSZ * SDIM; e += NT)
            out_stack[(size_t)bg * SSZ * SDIM + e] = sm->stck[0][e >> 6][e & 63];
    }
}

extern "C" void kernel_launch(void* const* d_in, const int* in_sizes, int n_in,
                              void* d_out, int out_size) {
    cudaFuncSetAttribute(srnn_kernel,
                         cudaFuncAttributeMaxDynamicSharedMemorySize,
                         (int)sizeof(SM));
    srnn_kernel<<<BATCH, NT, sizeof(SM)>>>(
        (const int*)  d_in[0],
        (const float*)d_in[1],
        (const float*)d_in[2],  (const float*)d_in[3],
        (const float*)d_in[4],  (const float*)d_in[5],
        (const float*)d_in[6],  (const float*)d_in[7],
        (const float*)d_in[8],  (const float*)d_in[9],
        (const float*)d_in[10], (const float*)d_in[11],
        (const float*)d_in[12], (const float*)d_in[13],
        (const float*)d_in[14], (const float*)d_in[15],
        (const float*)d_in[16],
        (float*)d_out);
}

// round 17
// speedup vs baseline: 1.0225x; 1.0225x over previous
#include <cuda_runtime.h>
#include <math.h>
#include <stdint.h>

// EncoderSRNN GB300 R16: R14 base (best 791.6us) + single-pass merged tops
// update in B + hoisted arrive address. 32 clusters x 4 CTAs, 4 lanes/cluster.

#define T_STEPS 256
#define BATCH   128
#define HDIM    256
#define SDIM    64
#define SSZ     64
#define NT      512
#define NKW     40     // k per mhid warp; k = warp + 16*i (strided)

typedef unsigned long long ull;

struct __align__(16) SM {
    float4 x4[2][640];          // [parity][k] = {b0,b1,b2,b3}
    float4 partm[16][65];       // mhid partials (padded)
    float4 parts[40][33];       // 0-15 pv, 16-31 uv, 32-39 head halves
    float  stck[2][SSZ][SDIM];  // own-lane stack dbl-buf
    float  pvb[2][SDIM][4];     // push_val [p][d][b]
    float  uvb[2][SDIM][4];     // u_val
    float  s2b[2][4][SDIM];     // old stack row2 [p][b][d]
    float  Whs[16][256];        // own 16 pv rows
    float  Wsu[16][128];
    float  Whd[4][256];         // head rows (W_ha 0-2, W_hg 3)
    float  outst[4][64];        // staged outputs [b][r]
    int    toks[T_STEPS][4];    // token ids for this cluster's 4 lanes
    float  biasm[64];
    float  bhs[16], bsu[16], bhd[4];
    float  lg[4][4];            // [b][head]
    float  pr[4][4];            // [b][push,pop,noop]
    ull    mbar;
};

__device__ __forceinline__ uint32_t s32(const void* p) {
    return (uint32_t)__cvta_generic_to_shared(p);
}
__device__ __forceinline__ uint32_t mapa_r(uint32_t a, uint32_t r) {
    uint32_t ra;
    asm("mapa.shared::cluster.u32 %0, %1, %2;" : "=r"(ra) : "r"(a), "r"(r));
    return ra;
}
__device__ __forceinline__ void stcv4(uint32_t addr, float a, float b, float c, float d) {
    asm volatile("st.shared::cluster.v4.f32 [%0], {%1,%2,%3,%4};"
                 :: "r"(addr), "f"(a), "f"(b), "f"(c), "f"(d) : "memory");
}
__device__ __forceinline__ uint32_t ctarank() {
    uint32_t r; asm("mov.u32 %0, %%cluster_ctarank;" : "=r"(r)); return r;
}
__device__ __forceinline__ ull ffma2(ull a, ull b, ull c) {
    ull d; asm("fma.rn.f32x2 %0, %1, %2, %3;" : "=l"(d) : "l"(a), "l"(b), "l"(c)); return d;
}
__device__ __forceinline__ ull bcast2(float f) {
    ull d; asm("mov.b64 %0, {%1, %1};" : "=l"(d) : "f"(f)); return d;
}
__device__ __forceinline__ float2 unpk(ull v) {
    float2 u; asm("mov.b64 {%0, %1}, %2;" : "=f"(u.x), "=f"(u.y) : "l"(v)); return u;
}
__device__ __forceinline__ float loadW(const float* We, const float* Wh,
                                       const float* Ws, int R, int k) {
    if (k < 256) return We[R * 256 + k];
    if (k < 512) return Wh[R * 256 + (k - 256)];
    return Ws[R * 128 + (k - 512)];
}

template<int NM>
__device__ __forceinline__ void small1(const float* W0, const ulonglong2* xb,
                                       int koff, int lane, float4* d0) {
    ull a0 = 0, a1 = 0;
    #pragma unroll
    for (int m = 0; m < NM; ++m) {
        int kk = lane + 32 * m;
        ulonglong2 xx = xb[koff + kk];
        ull w = bcast2(W0[kk]);
        a0 = ffma2(w, xx.x, a0);
        a1 = ffma2(w, xx.y, a1);
    }
    float2 u0 = unpk(a0), u1 = unpk(a1);
    *d0 = make_float4(u0.x, u0.y, u1.x, u1.y);
}

template<int NM>
__device__ __forceinline__ void small2(const float* W0, const float* W1,
                                       const ulonglong2* xb, int koff, int lane,
                                       float4* d0, float4* d1) {
    ull a00 = 0, a01 = 0, a10 = 0, a11 = 0;
    #pragma unroll
    for (int m = 0; m < NM; ++m) {
        int kk = lane + 32 * m;
        ulonglong2 xx = xb[koff + kk];
        ull w0 = bcast2(W0[kk]);
        a00 = ffma2(w0, xx.x, a00);
        a01 = ffma2(w0, xx.y, a01);
        ull w1 = bcast2(W1[kk]);
        a10 = ffma2(w1, xx.x, a10);
        a11 = ffma2(w1, xx.y, a11);
    }
    float2 u0 = unpk(a00), u1 = unpk(a01);
    *d0 = make_float4(u0.x, u0.y, u1.x, u1.y);
    float2 v0 = unpk(a10), v1 = unpk(a11);
    *d1 = make_float4(v0.x, v0.y, v1.x, v1.y);
}

__global__ void __launch_bounds__(NT, 1) __cluster_dims__(4, 1, 1)
srnn_kernel(const int*   __restrict__ inputs,
            const float* __restrict__ emb_W,
            const float* __restrict__ W_hh, const float* __restrict__ b_hh,
            const float* __restrict__ W_eh, const float* __restrict__ b_eh,
            const float* __restrict__ W_ha, const float* __restrict__ b_ha,
            const float* __restrict__ W_hg, const float* __restrict__ b_hg,
            const float* __restrict__ W_hs, const float* __restrict__ b_hs,
            const float* __restrict__ W_sh, const float* __restrict__ b_sh,
            const float* __restrict__ W_su, const float* __restrict__ b_su,
            const float* __restrict__ empty_elem,
            float* __restrict__ out)
{
    extern __shared__ char raw[];
    SM* sm = reinterpret_cast<SM*>(raw);

    const int tid  = threadIdx.x;
    const int warp = tid >> 5;
    const int lane = tid & 31;
    const uint32_t rank = ctarank();
    const int clus = blockIdx.x >> 2;

    float* out_outputs = out;
    float* out_hid     = out + (size_t)T_STEPS * BATCH * HDIM;
    float* out_stack   = out_hid + BATCH * HDIM;
    float* out_acts    = out_stack + (size_t)BATCH * SSZ * SDIM;

    const uint32_t x4_l  = s32(&sm->x4[0][0]);
    const uint32_t pv_l  = s32(&sm->pvb[0][0][0]);
    const uint32_t uv_l  = s32(&sm->uvb[0][0][0]);
    const uint32_t s2_l  = s32(&sm->s2b[0][0][0]);
    const uint32_t mbar_l = s32(&sm->mbar);
    const uint32_t arr_r = mapa_r(mbar_l, (uint32_t)(tid & 3));  // hoisted

    // ===================== init =====================
    float wr0[NKW], wr1[NKW];
    {
        int R0 = 64 * (int)rank + lane, R1 = R0 + 32;
        #pragma unroll
        for (int i = 0; i < NKW; ++i) {
            int k = warp + 16 * i;
            wr0[i] = loadW(W_eh, W_hh, W_sh, R0, k);
            wr1[i] = loadW(W_eh, W_hh, W_sh, R1, k);
        }
    }
    for (int idx = tid; idx < 16 * 256; idx += NT) {
        int r = idx >> 8, k = idx & 255;
        sm->Whs[r][k] = W_hs[(16 * rank + r) * 256 + k];
    }
    for (int idx = tid; idx < 16 * 128; idx += NT) {
        int r = idx >> 7, k = idx & 127;
        sm->Wsu[r][k] = W_su[(16 * rank + r) * 128 + k];
    }
    for (int idx = tid; idx < 4 * 256; idx += NT) {
        int r = idx >> 8, k = idx & 255;
        sm->Whd[r][k] = (r < 3) ? W_ha[r * 256 + k] : W_hg[k];
    }
    for (int e = tid; e < T_STEPS * 4; e += NT) {
        sm->toks[e >> 2][e & 3] = inputs[(e >> 2) * BATCH + clus * 4 + (e & 3)];
    }
    if (tid < 64) {
        int R = 64 * rank + tid;
        sm->biasm[tid] = b_eh[R] + b_hh[R] + b_sh[R];
        if (tid < 16) {
            sm->bhs[tid] = b_hs[16 * rank + tid];
            sm->bsu[tid] = b_su[16 * rank + tid];
        }
        if (tid < 4) sm->bhd[tid] = (tid < 3) ? b_ha[tid] : b_hg[0];
    }
    if (tid == 0) {
        asm volatile("mbarrier.init.shared.b64 [%0], %1;"
                     :: "r"(mbar_l), "r"(4) : "memory");
    }
    for (int e = tid; e < 640 * 4; e += NT) {
        int k = e >> 2, b = e & 3;
        float v;
        if (k < 256) {
            int row = inputs[clus * 4 + b];
            v = emb_W[(size_t)row * 256 + k];
        } else if (k < 512) v = 0.f;
        else                v = empty_elem[(k - 512) & 63];
        ((float*)&sm->x4[0][k])[b] = v;
    }
    for (int e = tid; e < SSZ * SDIM; e += NT)
        sm->stck[0][e >> 6][e & 63] = empty_elem[e & 63];
    __syncthreads();
    asm volatile("barrier.cluster.arrive.aligned;" ::: "memory");
    asm volatile("barrier.cluster.wait.aligned;" ::: "memory");

    // mhid accumulators persist across barriers (emb segment pipelined)
    ull a00, a01, a10, a11;
    {
        a00 = a01 = a10 = a11 = 0;
        const ulonglong2* xv = reinterpret_cast<const ulonglong2*>(&sm->x4[0][0]);
        #pragma unroll
        for (int i = 0; i < 16; ++i) {
            ulonglong2 xx = xv[warp + 16 * i];
            ull w0 = bcast2(wr0[i]);
            a00 = ffma2(w0, xx.x, a00);
            a01 = ffma2(w0, xx.y, a01);
            ull w1 = bcast2(wr1[i]);
            a10 = ffma2(w1, xx.x, a10);
            a11 = ffma2(w1, xx.y, a11);
        }
    }

    // ===================== time loop =====================
    for (int t = 0; t < T_STEPS; ++t) {
        const int p = t & 1;

        // ---------- A1 ----------
        float pe0, pe1;
        {
            int tn = (t + 1 < T_STEPS) ? t + 1 : T_STEPS - 1;
            int b = tid >> 7, k = tid & 127;
            int row = sm->toks[tn][b];
            pe0 = emb_W[(size_t)row * 256 + k];
            pe1 = emb_W[(size_t)row * 256 + k + 128];
        }
        {
            const ulonglong2* xv = reinterpret_cast<const ulonglong2*>(&sm->x4[p][0]);
            #pragma unroll
            for (int i = 16; i < NKW; ++i) {
                ulonglong2 xx = xv[warp + 16 * i];
                ull w0 = bcast2(wr0[i]);
                a00 = ffma2(w0, xx.x, a00);
                a01 = ffma2(w0, xx.y, a01);
                ull w1 = bcast2(wr1[i]);
                a10 = ffma2(w1, xx.x, a10);
                a11 = ffma2(w1, xx.y, a11);
            }
            float2 u0 = unpk(a00), u1 = unpk(a01);
            sm->partm[warp][lane]      = make_float4(u0.x, u0.y, u1.x, u1.y);
            float2 v0 = unpk(a10), v1 = unpk(a11);
            sm->partm[warp][lane + 32] = make_float4(v0.x, v0.y, v1.x, v1.y);
        }
        const ulonglong2* xb = reinterpret_cast<const ulonglong2*>(&sm->x4[p][0]);
        if (warp < 8) {                 // pv rows {2w, 2w+1}
            int r0 = 2 * warp;
            small2<8>(sm->Whs[r0], sm->Whs[r0 + 1], xb, 256, lane,
                      &sm->parts[r0][lane], &sm->parts[r0 + 1][lane]);
        } else {                        // uv rows {2(w-8), 2(w-8)+1} + head half
            int r0 = 2 * (warp - 8);
            small2<4>(sm->Wsu[r0], sm->Wsu[r0 + 1], xb, 512, lane,
                      &sm->parts[16 + r0][lane], &sm->parts[16 + r0 + 1][lane]);
            int h = (warp - 8) & 3;
            const float* Wr = sm->Whd[h] + ((warp < 12) ? 0 : 128);
            small1<4>(Wr, xb, (warp < 12) ? 256 : 384, lane,
                      &sm->parts[32 + (warp - 8)][lane]);
        }
        {   // emb(t+1) into x4[p^1]
            int b = tid >> 7, k = tid & 127;
            float* dst = (float*)&sm->x4[p ^ 1][0];
            dst[k * 4 + b]         = pe0;
            dst[(k + 128) * 4 + b] = pe1;
        }
        __syncthreads();   // bar 1

        // ---------- A2: reduce + lane-spread DSMEM broadcast + probs ----------
        if (tid < 256) {                // mhid: 4 threads per row
            int r = tid >> 2, q = tid & 3;
            float4 s4 = sm->partm[q * 4][r];
            #pragma unroll
            for (int j = 1; j < 4; ++j) {
                float4 v = sm->partm[q * 4 + j][r];
                s4.x += v.x; s4.y += v.y; s4.z += v.z; s4.w += v.w;
            }
            #pragma unroll
            for (int o = 1; o <= 2; o <<= 1) {
                s4.x += __shfl_xor_sync(0xffffffffu, s4.x, o);
                s4.y += __shfl_xor_sync(0xffffffffu, s4.y, o);
                s4.z += __shfl_xor_sync(0xffffffffu, s4.z, o);
                s4.w += __shfl_xor_sync(0xffffffffu, s4.w, o);
            }
            float bb = sm->biasm[r];
            float h0 = fmaxf(s4.x + bb, 0.f), h1 = fmaxf(s4.y + bb, 0.f);
            float h2 = fmaxf(s4.z + bb, 0.f), h3 = fmaxf(s4.w + bb, 0.f);
            int R = 64 * rank + r;
            uint32_t off = x4_l + (uint32_t)((p ^ 1) * 640 + 256 + R) * 16u;
            stcv4(mapa_r(off, (uint32_t)q), h0, h1, h2, h3);
            if (q == 1) {               // outputs staging
                sm->outst[0][r] = h0;
                sm->outst[1][r] = h1;
                sm->outst[2][r] = h2;
                sm->outst[3][r] = h3;
            }
        } else if (tid < 416) {         // small rows reduce (warps 8-12)
            int e = tid - 256;
            int vr = e >> 2, s = e & 3;
            float4 acc = make_float4(0.f, 0.f, 0.f, 0.f);
            #pragma unroll
            for (int u = 0; u < 8; ++u) {
                float4 v = sm->parts[vr][s + 4 * u];
                acc.x += v.x; acc.y += v.y; acc.z += v.z; acc.w += v.w;
            }
            #pragma unroll
            for (int o = 1; o <= 2; o <<= 1) {
                acc.x += __shfl_xor_sync(0xffffffffu, acc.x, o);
                acc.y += __shfl_xor_sync(0xffffffffu, acc.y, o);
                acc.z += __shfl_xor_sync(0xffffffffu, acc.z, o);
                acc.w += __shfl_xor_sync(0xffffffffu, acc.w, o);
            }
            if (vr >= 32) {             // heads: combine two k-halves (warp 12)
                acc.x += __shfl_xor_sync(0xffffffffu, acc.x, 16);
                acc.y += __shfl_xor_sync(0xffffffffu, acc.y, 16);
                acc.z += __shfl_xor_sync(0xffffffffu, acc.z, 16);
                acc.w += __shfl_xor_sync(0xffffffffu, acc.w, 16);
            }
            if (vr < 16) {              // pv -> CTA s (each lane one dest)
                float bb = sm->bhs[vr];
                int dd = 16 * (int)rank + vr;
                uint32_t off = pv_l + (uint32_t)(p * 64 + dd) * 16u;
                stcv4(mapa_r(off, (uint32_t)s),
                      fmaxf(acc.x + bb, 0.f), fmaxf(acc.y + bb, 0.f),
                      fmaxf(acc.z + bb, 0.f), fmaxf(acc.w + bb, 0.f));
            } else if (vr < 32) {       // uv -> CTA s
                float bb = sm->bsu[vr - 16];
                int dd = 16 * (int)rank + (vr - 16);
                uint32_t off = uv_l + (uint32_t)(p * 64 + dd) * 16u;
                stcv4(mapa_r(off, (uint32_t)s),
                      fmaxf(acc.x + bb, 0.f), fmaxf(acc.y + bb, 0.f),
                      fmaxf(acc.z + bb, 0.f), fmaxf(acc.w + bb, 0.f));
            } else if (s == 0 && vr < 36) {
                int h = vr - 32;
                float bb = sm->bhd[h];
                sm->lg[0][h] = acc.x + bb;
                sm->lg[1][h] = acc.y + bb;
                sm->lg[2][h] = acc.z + bb;
                sm->lg[3][h] = acc.w + bb;
            }
            if (warp == 12) {           // probs inline
                __syncwarp();
                if (lane < 4) {
                    int b = lane;
                    float l0 = sm->lg[b][0], l1 = sm->lg[b][1], l2 = sm->lg[b][2];
                    float g  = sm->lg[b][3];
                    float ssp = (g > 20.f) ? g : log1pf(expf(g));
                    float gamma = 1.f + ssp;
                    float mx = fmaxf(l0, fmaxf(l1, l2));
                    float e0 = expf(l0 - mx), e1 = expf(l1 - mx), e2 = expf(l2 - mx);
                    float ls = logf(e0 + e1 + e2);
                    float s0 = expf(gamma * ((l0 - mx) - ls));
                    float s1 = expf(gamma * ((l1 - mx) - ls));
                    float s2 = expf(gamma * ((l2 - mx) - ls));
                    float inv = 1.f / (s0 + s1 + s2 + 1e-16f);
                    sm->pr[b][0] = s0 * inv;
                    sm->pr[b][1] = s1 * inv;
                    sm->pr[b][2] = s2 * inv;
                    if ((uint32_t)b == rank) {
                        int idx = 0; float best = s0;
                        if (s1 > best) { best = s1; idx = 1; }
                        if (s2 > best) idx = 2;
                        out_acts[t * BATCH + clus * 4 + rank] = (float)idx;
                    }
                }
            }
        } else if (tid < 480) {         // s2 broadcast: 64 threads, 1 store each
            int t2 = tid - 416;         // 0..63
            int d = t2 >> 4, i16 = t2 & 15;
            const float4* s2src = reinterpret_cast<const float4*>(&sm->stck[p][2][0]);
            float4 v = s2src[i16];
            uint32_t off = s2_l + (uint32_t)((p * 4 + rank) * 64 + 4 * i16) * 4u;
            stcv4(mapa_r(off, (uint32_t)d), v.x, v.y, v.z, v.w);
        }
        __syncthreads();   // bar 2

        // ---------- signal peers (release; bar2 gives cumulativity) ----------
        if (tid < 4) {
            asm volatile("mbarrier.arrive.release.cluster.shared::cluster.b64 _, [%0];"
                         :: "r"(arr_r) : "memory");
        }

        // ---------- window: outputs STG + NEXT step's mhid emb segment ----------
        if (tid >= 480) {
            int j = tid - 480;            // 0..31
            #pragma unroll
            for (int jj = 0; jj < 2; ++jj) {
                int e = j + 32 * jj;      // 0..63
                int b = e >> 4, rr = e & 15;
                const float4* src = reinterpret_cast<const float4*>(&sm->outst[b][0]);
                float4 v = src[rr];
                size_t ob = ((size_t)t * BATCH + clus * 4 + b) * HDIM + 64 * rank + 4 * rr;
                *reinterpret_cast<float4*>(&out_outputs[ob]) = v;
            }
        }
        {   // emb segment for t+1 over x4[p^1].emb
            a00 = a01 = a10 = a11 = 0;
            const ulonglong2* xv = reinterpret_cast<const ulonglong2*>(&sm->x4[p ^ 1][0]);
            #pragma unroll
            for (int i = 0; i < 16; ++i) {
                ulonglong2 xx = xv[warp + 16 * i];
                ull w0 = bcast2(wr0[i]);
                a00 = ffma2(w0, xx.x, a00);
                a01 = ffma2(w0, xx.y, a01);
                ull w1 = bcast2(wr1[i]);
                a10 = ffma2(w1, xx.x, a10);
                a11 = ffma2(w1, xx.y, a11);
            }
        }

        // ---------- wait for all 4 CTAs' exchanges (acquire) ----------
        {
            uint32_t parity = (uint32_t)(t & 1);
            asm volatile(
                "{\n\t"
                ".reg .pred P;\n"
                "W%=:\n\t"
                "mbarrier.try_wait.parity.acquire.cluster.shared::cta.b64 P, [%0], %1, 0x989680;\n\t"
                "@!P bra W%=;\n\t"
                "}"
                :: "r"(mbar_l), "r"(parity) : "memory");
        }

        // ---------- B: stack update (rolling loads) + merged tops ----------
        if (tid < 256) {
            int d4 = tid & 15, ic = tid >> 4;
            const float4* Ssrc = (const float4*)sm->stck[p];
            float4*       Sdst = (float4*)sm->stck[p ^ 1];
            float pp = sm->pr[rank][0], pq = sm->pr[rank][1], pn = sm->pr[rank][2];
            float4 prev, uv4;
            if (ic == 0) {
                prev = make_float4(sm->pvb[p][d4 * 4 + 0][rank],
                                   sm->pvb[p][d4 * 4 + 1][rank],
                                   sm->pvb[p][d4 * 4 + 2][rank],
                                   sm->pvb[p][d4 * 4 + 3][rank]);
                uv4  = make_float4(sm->uvb[p][d4 * 4 + 0][rank],
                                   sm->uvb[p][d4 * 4 + 1][rank],
                                   sm->uvb[p][d4 * 4 + 2][rank],
                                   sm->uvb[p][d4 * 4 + 3][rank]);
            } else {
                prev = Ssrc[(4 * ic - 1) * 16 + d4];
            }
            float4 curv = Ssrc[(4 * ic) * 16 + d4];
            #pragma unroll
            for (int ii = 0; ii < 4; ++ii) {
                int i = 4 * ic + ii;
                float4 nxt = (i < 63) ? Ssrc[(i + 1) * 16 + d4]
                                      : make_float4(0.f, 0.f, 0.f, 0.f);
                float4 qs = (i == 0) ? uv4 : nxt;
                float4 nv;
                nv.x = pp * prev.x + pq * qs.x + pn * curv.x;
                nv.y = pp * prev.y + pq * qs.y + pn * curv.y;
                nv.z = pp * prev.z + pq * qs.z + pn * curv.z;
                nv.w = pp * prev.w + pq * qs.w + pn * curv.w;
                Sdst[i * 16 + d4] = nv;
                prev = curv; curv = nxt;
            }
        } else {
            // merged tops: one thread per (b,d) computes rows 0 and 1 together
            int e = tid - 256;            // 0..255
            int b = e >> 6, d = e & 63;
            float pp = sm->pr[b][0], pq = sm->pr[b][1], pn = sm->pr[b][2];
            float old0 = ((float*)&sm->x4[p][512 + d])[b];
            float old1 = ((float*)&sm->x4[p][576 + d])[b];
            float nv0 = pp * sm->pvb[p][d][b] + pq * sm->uvb[p][d][b] + pn * old0;
            float nv1 = pp * old0 + pq * sm->s2b[p][b][d] + pn * old1;
            ((float*)&sm->x4[p ^ 1][512 + d])[b] = nv0;
            ((float*)&sm->x4[p ^ 1][576 + d])[b] = nv1;
        }
        __syncthreads();   // bar 3
    }

    // ===================== final outputs =====================
    {
        int bg = clus * 4 + rank;
        if (tid < 256)
            out_hid[bg * HDIM + tid] = ((float*)&sm->x4[0][256 + tid])[rank];
        for (int e = tid; e < SSZ * SDIM; e += NT)
            out_stack[(size_t)bg * SSZ * SDIM + e] = sm->stck[0][e >> 6][e & 63];
    }
}

extern "C" void kernel_launch(void* const* d_in, const int* in_sizes, int n_in,
                              void* d_out, int out_size) {
    cudaFuncSetAttribute(srnn_kernel,
                         cudaFuncAttributeMaxDynamicSharedMemorySize,
                         (int)sizeof(SM));
    srnn_kernel<<<BATCH, NT, sizeof(SM)>>>(
        (const int*)  d_in[0],
        (const float*)d_in[1],
        (const float*)d_in[2],  (const float*)d_in[3],
        (const float*)d_in[4],  (const float*)d_in[5],
        (const float*)d_in[6],  (const float*)d_in[7],
        (const float*)d_in[8],  (const float*)d_in[9],
        (const float*)d_in[10], (const float*)d_in[11],
        (const float*)d_in[12], (const float*)d_in[13],
        (const float*)d_in[14], (const float*)d_in[15],
        (const float*)d_in[16],
        (float*)d_out);
}